// round 13
// baseline (speedup 1.0000x reference)
#include <cuda_runtime.h>
#include <cuda_bf16.h>
#include <cuda_fp16.h>
#include <cstdint>
#include <math.h>

// Problem constants
#define CB 4
#define CS 1024
#define CD 1024
#define CH 16
#define CHD 64
#define GK 1024   // K of all three big GEMMs

// ---------------------------------------------------------------------------
// Scratch (device globals — no runtime allocation allowed)
// ---------------------------------------------------------------------------
__device__ float g_Qp[(size_t)CB * CH * CS * CHD];       // queries  [b,h,s,k]
__device__ float g_Vp[(size_t)CB * CH * CS * CHD];       // values   [b,h,s,k]
__device__ __half g_Rs[(size_t)CH * CS * CS];            // s1*softmax(random), fp16
__device__ __nv_bfloat16 g_Ah[(size_t)CB * CS * GK];     // A hi (bf16) [m][k]
__device__ __nv_bfloat16 g_Al[(size_t)CB * CS * GK];     // A lo (bf16) [m][k]
__device__ __nv_bfloat16 g_AOh[(size_t)CB * CS * CD];    // attn out hi [m][k]
__device__ __nv_bfloat16 g_AOl[(size_t)CB * CS * CD];    // attn out lo [m][k]
__device__ __nv_bfloat16 g_Wth[(size_t)GK * GK];         // W^T hi (bf16) [n][k]
__device__ __nv_bfloat16 g_Wtl[(size_t)GK * GK];         // W^T lo (bf16) [n][k]
__device__ __nv_bfloat16 g_Vth[(size_t)CB * CH * CHD * CS];  // V^T hi [b,h,d,s]
__device__ __nv_bfloat16 g_Vtl[(size_t)CB * CH * CHD * CS];  // V^T lo [b,h,d,s]
__device__ __nv_bfloat16 g_W2th[(size_t)CS * CHD];       // W2^T hi [t][j]
__device__ __nv_bfloat16 g_W2tl[(size_t)CS * CHD];       // W2^T lo [t][j]

// ---------------------------------------------------------------------------
// Warp-MMA / async-copy helpers (sm_80+ path — compiles at compute_100)
// ---------------------------------------------------------------------------
__device__ __forceinline__ uint32_t smem_u32(const void* p) {
    uint32_t a;
    asm("{ .reg .u64 t; cvta.to.shared.u64 t, %1; cvt.u32.u64 %0, t; }"
        : "=r"(a) : "l"(p));
    return a;
}

__device__ __forceinline__ void ldsm_x4(uint32_t* r, uint32_t addr) {
    asm volatile("ldmatrix.sync.aligned.m8n8.x4.shared.b16 {%0,%1,%2,%3}, [%4];"
                 : "=r"(r[0]), "=r"(r[1]), "=r"(r[2]), "=r"(r[3]) : "r"(addr));
}

__device__ __forceinline__ void mma16816(float* c, const uint32_t* a, const uint32_t* b) {
    asm volatile(
        "mma.sync.aligned.m16n8k16.row.col.f32.bf16.bf16.f32 "
        "{%0,%1,%2,%3}, {%4,%5,%6,%7}, {%8,%9}, {%0,%1,%2,%3};"
        : "+f"(c[0]), "+f"(c[1]), "+f"(c[2]), "+f"(c[3])
        : "r"(a[0]), "r"(a[1]), "r"(a[2]), "r"(a[3]), "r"(b[0]), "r"(b[1]));
}

__device__ __forceinline__ uint32_t pack_split(float x, float y, uint32_t& lo) {
    __nv_bfloat16 hx = __float2bfloat16(x), hy = __float2bfloat16(y);
    __nv_bfloat16 lx = __float2bfloat16(x - __bfloat162float(hx));
    __nv_bfloat16 ly = __float2bfloat16(y - __bfloat162float(hy));
    lo = (uint32_t)__bfloat16_as_ushort(lx) | ((uint32_t)__bfloat16_as_ushort(ly) << 16);
    return (uint32_t)__bfloat16_as_ushort(hx) | ((uint32_t)__bfloat16_as_ushort(hy) << 16);
}

__device__ __forceinline__ void cp_async16(uint32_t dst, const void* src) {
    asm volatile("cp.async.cg.shared.global [%0], [%1], 16;"
                 :: "r"(dst), "l"(src) : "memory");
}
#define CP_COMMIT() asm volatile("cp.async.commit_group;" ::: "memory")
#define CP_WAIT(n)  asm volatile("cp.async.wait_group %0;" :: "n"(n) : "memory")

// ---------------------------------------------------------------------------
// Elementwise split: h/l[i] = split(src[i]).  1 float4 per thread.
// ---------------------------------------------------------------------------
__global__ void __launch_bounds__(256) asplit_kernel(
    const float* __restrict__ src, __nv_bfloat16* __restrict__ h,
    __nv_bfloat16* __restrict__ l)
{
    int idx = blockIdx.x * 256 + threadIdx.x;     // float4 index
    float4 a = ((const float4*)src)[idx];
    uint2 hv, lv;
    hv.x = pack_split(a.x, a.y, lv.x);
    hv.y = pack_split(a.z, a.w, lv.y);
    ((uint2*)h)[idx] = hv;
    ((uint2*)l)[idx] = lv;
}

// ---------------------------------------------------------------------------
// Generic transpose + split-bf16: dst_hi/lo[c][r] = split(src[r][c]), batched z.
// ---------------------------------------------------------------------------
__global__ void __launch_bounds__(256) tsplit_kernel(
    const float* __restrict__ src, __nv_bfloat16* __restrict__ dh,
    __nv_bfloat16* __restrict__ dl, int R, int C)
{
    __shared__ float t[32][33];
    const size_t zoff = (size_t)blockIdx.z * R * C;
    src += zoff; dh += zoff; dl += zoff;
    const int c0 = blockIdx.x * 32, r0 = blockIdx.y * 32;
    const int tx = threadIdx.x, ty = threadIdx.y;
#pragma unroll
    for (int j = 0; j < 32; j += 8)
        t[ty + j][tx] = src[(size_t)(r0 + ty + j) * C + c0 + tx];
    __syncthreads();
#pragma unroll
    for (int j = 0; j < 32; j += 8) {
        float v = t[tx][ty + j];
        __nv_bfloat16 h = __float2bfloat16(v);
        size_t o = (size_t)(c0 + ty + j) * R + r0 + tx;
        dh[o] = h;
        dl[o] = __float2bfloat16(v - __bfloat162float(h));
    }
}

// ---------------------------------------------------------------------------
// Split-bf16 mma.sync GEMM v3: tile 128x64, BK=64, warp tile 32x32 (4M x 2N),
// 2-stage cp.async, 108 KB smem -> 2 CTAs/SM, spill-free at 128 regs.
// ---------------------------------------------------------------------------
#define SROW 144
#define A_TILE3 (128 * SROW)            // 18432
#define W_TILE3 (64 * SROW)             // 9216
#define STAGE3 (2 * A_TILE3 + 2 * W_TILE3)   // 55296
#define GEMM_SMEM (2 * STAGE3)          // 110592

__global__ void __launch_bounds__(256, 2) gemm_mma_kernel(
    const __nv_bfloat16* __restrict__ Ah, const __nv_bfloat16* __restrict__ Al,
    const __nv_bfloat16* __restrict__ Wth, const __nv_bfloat16* __restrict__ Wtl,
    const float* __restrict__ bias, float* __restrict__ out, int mode)
{
    extern __shared__ char dsm[];
    const uint32_t sb = smem_u32(dsm);

    const int tid = threadIdx.x;
    const int lane = tid & 31, wid = tid >> 5;
    const int warp_m = wid & 3;          // 4 along M (32 rows each)
    const int warp_n = wid >> 2;         // 2 along N (32 cols each)
    const int m0 = blockIdx.y * 128;
    const int n0 = blockIdx.x * 64;

    const uint32_t aOff = (uint32_t)(warp_m * 32 + (lane & 15)) * SROW + (lane >> 4) * 16;
    const uint32_t bOff = (uint32_t)(warp_n * 32 + (lane & 7) + ((lane >> 4) & 1) * 8) * SROW
                        + ((lane >> 3) & 1) * 16;

    auto stage_load = [&](int s, int buf) {
        const int k0 = s * 64;
        const uint32_t db = sb + buf * STAGE3;
        // A tiles: 2048 16B-chunks
#pragma unroll
        for (int i = 0; i < 8; ++i) {
            int idx = i * 256 + tid;                 // 0..2047
            int tile = idx >> 10;                    // 0=Ah 1=Al
            int j = idx & 1023;
            int row = j >> 3, c8 = j & 7;
            const __nv_bfloat16* src = (tile ? Al : Ah)
                + (size_t)(m0 + row) * GK + k0 + c8 * 8;
            cp_async16(db + tile * A_TILE3 + (uint32_t)row * SROW + c8 * 16, src);
        }
        // W tiles: 1024 16B-chunks
#pragma unroll
        for (int i = 0; i < 4; ++i) {
            int idx = i * 256 + tid;                 // 0..1023
            int tile = idx >> 9;                     // 0=Wh 1=Wl
            int j = idx & 511;
            int row = j >> 3, c8 = j & 7;
            const __nv_bfloat16* src = (tile ? Wtl : Wth)
                + (size_t)(n0 + row) * GK + k0 + c8 * 8;
            cp_async16(db + 2 * A_TILE3 + tile * W_TILE3
                       + (uint32_t)row * SROW + c8 * 16, src);
        }
    };

    float acc[2][4][4] = {};

    stage_load(0, 0);
    CP_COMMIT();

    for (int s = 0; s < 16; ++s) {
        if (s < 15) {
            stage_load(s + 1, (s + 1) & 1);
            CP_COMMIT();
            CP_WAIT(1);
        } else {
            CP_WAIT(0);
        }
        __syncthreads();

        const uint32_t db = sb + (s & 1) * STAGE3;
        const uint32_t sAh = db, sAl = db + A_TILE3;
        const uint32_t sBh = db + 2 * A_TILE3, sBl = sBh + W_TILE3;

#pragma unroll
        for (int kk = 0; kk < 4; ++kk) {
            uint32_t ah[2][4], al[2][4], bh[4][2], bl[4][2];
#pragma unroll
            for (int mf = 0; mf < 2; ++mf) {
                uint32_t o = aOff + (uint32_t)mf * (16 * SROW) + kk * 32;
                ldsm_x4(ah[mf], sAh + o);
                ldsm_x4(al[mf], sAl + o);
            }
#pragma unroll
            for (int g = 0; g < 2; ++g) {
                uint32_t o = bOff + (uint32_t)g * (16 * SROW) + kk * 32;
                uint32_t r[4];
                ldsm_x4(r, sBh + o);
                bh[2 * g][0] = r[0]; bh[2 * g][1] = r[1];
                bh[2 * g + 1][0] = r[2]; bh[2 * g + 1][1] = r[3];
                ldsm_x4(r, sBl + o);
                bl[2 * g][0] = r[0]; bl[2 * g][1] = r[1];
                bl[2 * g + 1][0] = r[2]; bl[2 * g + 1][1] = r[3];
            }
#pragma unroll
            for (int mf = 0; mf < 2; ++mf)
#pragma unroll
                for (int nf = 0; nf < 4; ++nf)
                    mma16816(acc[mf][nf], ah[mf], bh[nf]);
#pragma unroll
            for (int mf = 0; mf < 2; ++mf)
#pragma unroll
                for (int nf = 0; nf < 4; ++nf)
                    mma16816(acc[mf][nf], ah[mf], bl[nf]);
#pragma unroll
            for (int mf = 0; mf < 2; ++mf)
#pragma unroll
                for (int nf = 0; nf < 4; ++nf)
                    mma16816(acc[mf][nf], al[mf], bh[nf]);
        }
        __syncthreads();
    }

#pragma unroll
    for (int mf = 0; mf < 2; ++mf) {
#pragma unroll
        for (int nf = 0; nf < 4; ++nf) {
            int m = m0 + warp_m * 32 + mf * 16 + (lane >> 2);
            int n = n0 + warp_n * 32 + nf * 8 + (lane & 3) * 2;
            float b0 = bias[n], b1 = bias[n + 1];
            float2 v0 = make_float2(acc[mf][nf][0] + b0, acc[mf][nf][1] + b1);
            float2 v1 = make_float2(acc[mf][nf][2] + b0, acc[mf][nf][3] + b1);
            if (mode == 0) {
                int h = n >> 6, kk = n & 63;
                {
                    int b_ = m >> 10, s_ = m & 1023;
                    *(float2*)(out + (((size_t)(b_ * CH + h)) * CS + s_) * CHD + kk) = v0;
                }
                {
                    int m2 = m + 8;
                    int b_ = m2 >> 10, s_ = m2 & 1023;
                    *(float2*)(out + (((size_t)(b_ * CH + h)) * CS + s_) * CHD + kk) = v1;
                }
            } else {
                *(float2*)(out + (size_t)m * CD + n) = v0;
                *(float2*)(out + (size_t)(m + 8) * CD + n) = v1;
            }
        }
    }
}

// ---------------------------------------------------------------------------
// rand softmax: g_Rs[h,q,:] = s1 * softmax(random_mat[h,q,:])  (fp16 output)
// ---------------------------------------------------------------------------
__global__ void __launch_bounds__(256) rand_softmax_kernel(
    const float* __restrict__ rm,
    const float* __restrict__ a1p, const float* __restrict__ a2p,
    __half* __restrict__ out)
{
    __shared__ float red[8];
    const int row = blockIdx.x;
    const int tid = threadIdx.x;
    const int lane = tid & 31, wid = tid >> 5;

    float4 v = ((const float4*)(rm + (size_t)row * 1024))[tid];
    float mx = fmaxf(fmaxf(v.x, v.y), fmaxf(v.z, v.w));
#pragma unroll
    for (int o = 16; o; o >>= 1) mx = fmaxf(mx, __shfl_xor_sync(0xffffffffu, mx, o));
    if (lane == 0) red[wid] = mx;
    __syncthreads();
    float m = red[0];
#pragma unroll
    for (int i = 1; i < 8; ++i) m = fmaxf(m, red[i]);

    float e0 = __expf(v.x - m), e1 = __expf(v.y - m);
    float e2 = __expf(v.z - m), e3 = __expf(v.w - m);
    float s = (e0 + e1) + (e2 + e3);
#pragma unroll
    for (int o = 16; o; o >>= 1) s += __shfl_xor_sync(0xffffffffu, s, o);
    __syncthreads();
    if (lane == 0) red[wid] = s;
    __syncthreads();
    float tot = 0.f;
#pragma unroll
    for (int i = 0; i < 8; ++i) tot += red[i];

    float a1 = a1p[0], a2 = a2p[0];
    float s1 = a1 / (a1 + a2);
    float k = s1 / tot;
    __half2* dst = (__half2*)(out + (size_t)row * 1024);
    dst[tid * 2]     = __floats2half2_rn(e0 * k, e1 * k);
    dst[tid * 2 + 1] = __floats2half2_rn(e2 * k, e3 * k);
}

// ---------------------------------------------------------------------------
// Fused synthesizer attention (R12 layout; Rs now fp16).
// ---------------------------------------------------------------------------
#define TW 144
#define PW 272
#define AO_TH   0
#define AO_TL   9216
#define AO_W2H  18432
#define AO_W2L  36864
#define AO_PH   18432
#define AO_PL   36864
#define AO_VH   55296
#define AO_VL   72704
#define AO_MROW 90112
#define AO_LROW 90368
#define AO_RMAX 90624
#define AO_RSUM 91648
#define ATTN_SMEM 92672

__global__ void __launch_bounds__(256, 2) synth_attn_mma(
    const float* __restrict__ W1, const float* __restrict__ b1,
    const __nv_bfloat16* __restrict__ W2th, const __nv_bfloat16* __restrict__ W2tl,
    const float* __restrict__ b2,
    const __nv_bfloat16* __restrict__ Vth, const __nv_bfloat16* __restrict__ Vtl,
    const float* __restrict__ a1p, const float* __restrict__ a2p)
{
    extern __shared__ char dsm[];
    const uint32_t sb = smem_u32(dsm);
    float* mrow = (float*)(dsm + AO_MROW);
    float* lrow = (float*)(dsm + AO_LROW);
    float* rmax = (float*)(dsm + AO_RMAX);
    float* rsum = (float*)(dsm + AO_RSUM);

    const int tid = threadIdx.x;
    const int lane = tid & 31, wid = tid >> 5;
    const int wm = wid & 1, wn = wid >> 1;
    const int bh = blockIdx.y;
    const int bi = bh >> 4, h = bh & 15;
    const int q0 = blockIdx.x * 64;

    const float a1 = a1p[0], a2 = a2p[0];
    const float s2 = a2 / (a1 + a2);

    // ---- prologue: T = relu(Q@W1 + b1) -> Th/Tl (temps live in V region) ----
    {
        float* Qs  = (float*)(dsm + AO_VH);
        float* W1s = (float*)(dsm + AO_VH + 16384);
        const float* Qbase = g_Qp + ((size_t)bh * CS + q0) * CHD;
        for (int i = tid; i < 1024; i += 256) {
            ((float4*)Qs)[i]  = ((const float4*)Qbase)[i];
            ((float4*)W1s)[i] = ((const float4*)W1)[i];
        }
        if (tid < 64) { mrow[tid] = -INFINITY; lrow[tid] = 0.f; }
        __syncthreads();

        const int a = tid >> 5, bb = tid & 31;
        float acc[8][2] = {};
#pragma unroll 4
        for (int i = 0; i < 64; ++i) {
            float2 w = *(const float2*)(W1s + i * 64 + 2 * bb);
#pragma unroll
            for (int r = 0; r < 8; ++r) {
                float qv = Qs[(a * 8 + r) * 64 + i];
                acc[r][0] = fmaf(qv, w.x, acc[r][0]);
                acc[r][1] = fmaf(qv, w.y, acc[r][1]);
            }
        }
        float bb0 = b1[2 * bb], bb1 = b1[2 * bb + 1];
        __syncthreads();
#pragma unroll
        for (int r = 0; r < 8; ++r) {
            float t0 = fmaxf(acc[r][0] + bb0, 0.f);
            float t1 = fmaxf(acc[r][1] + bb1, 0.f);
            uint32_t lo, hi = pack_split(t0, t1, lo);
            int q = a * 8 + r;
            *(uint32_t*)(dsm + AO_TH + q * TW + bb * 4) = hi;
            *(uint32_t*)(dsm + AO_TL + q * TW + bb * 4) = lo;
        }
    }
    __syncthreads();

    const uint32_t aOffT = (uint32_t)(wm * 32 + (lane & 15)) * TW + (lane >> 4) * 16;
    const uint32_t bOffW = (uint32_t)(wn * 32 + (lane & 7) + ((lane >> 4) & 1) * 8) * TW
                         + ((lane >> 3) & 1) * 16;
    const uint32_t aOffP = (uint32_t)(wm * 32 + (lane & 15)) * PW + (lane >> 4) * 16;
    const uint32_t bOffV = (uint32_t)(wn * 16 + (lane & 7) + ((lane >> 4) & 1) * 8) * PW
                         + ((lane >> 3) & 1) * 16;

    const __half* Rbase = g_Rs + ((size_t)h * CS + q0) * CS;
    const __nv_bfloat16* Vbh = Vth + (size_t)bh * CHD * CS;
    const __nv_bfloat16* Vbl = Vtl + (size_t)bh * CHD * CS;

    const int rbase = wm * 32 + (lane >> 2);

    float accO[2][2][4] = {};

    for (int k0 = 0; k0 < 1024; k0 += 128) {
#pragma unroll
        for (int i = 0; i < 4; ++i) {
            int idx = tid + i * 256;
            int row = idx >> 3, c = idx & 7;
            size_t so = (size_t)(k0 + row) * CHD + c * 8;
            cp_async16(sb + AO_W2H + row * TW + c * 16, W2th + so);
            cp_async16(sb + AO_W2L + row * TW + c * 16, W2tl + so);
        }
        CP_COMMIT();
#pragma unroll
        for (int i = 0; i < 4; ++i) {
            int idx = tid + i * 256;
            int row = idx >> 4, c = idx & 15;
            size_t so = (size_t)row * CS + k0 + c * 8;
            cp_async16(sb + AO_VH + row * PW + c * 16, Vbh + so);
            cp_async16(sb + AO_VL + row * PW + c * 16, Vbl + so);
        }
        CP_COMMIT();
        CP_WAIT(1);
        __syncthreads();

        float accL[2][4][4] = {};
#pragma unroll
        for (int kk = 0; kk < 4; ++kk) {
            uint32_t ah[2][4], al[2][4], bhf[4][2], blf[4][2];
#pragma unroll
            for (int mf = 0; mf < 2; ++mf) {
                uint32_t o = aOffT + (uint32_t)mf * (16 * TW) + kk * 32;
                ldsm_x4(ah[mf], sb + AO_TH + o);
                ldsm_x4(al[mf], sb + AO_TL + o);
            }
#pragma unroll
            for (int g = 0; g < 2; ++g) {
                uint32_t o = bOffW + (uint32_t)g * (16 * TW) + kk * 32;
                uint32_t r4[4];
                ldsm_x4(r4, sb + AO_W2H + o);
                bhf[2 * g][0] = r4[0]; bhf[2 * g][1] = r4[1];
                bhf[2 * g + 1][0] = r4[2]; bhf[2 * g + 1][1] = r4[3];
                ldsm_x4(r4, sb + AO_W2L + o);
                blf[2 * g][0] = r4[0]; blf[2 * g][1] = r4[1];
                blf[2 * g + 1][0] = r4[2]; blf[2 * g + 1][1] = r4[3];
            }
#pragma unroll
            for (int mf = 0; mf < 2; ++mf)
#pragma unroll
                for (int nf = 0; nf < 4; ++nf)
                    mma16816(accL[mf][nf], ah[mf], bhf[nf]);
#pragma unroll
            for (int mf = 0; mf < 2; ++mf)
#pragma unroll
                for (int nf = 0; nf < 4; ++nf)
                    mma16816(accL[mf][nf], ah[mf], blf[nf]);
#pragma unroll
            for (int mf = 0; mf < 2; ++mf)
#pragma unroll
                for (int nf = 0; nf < 4; ++nf)
                    mma16816(accL[mf][nf], al[mf], bhf[nf]);
        }

#pragma unroll
        for (int mf = 0; mf < 2; ++mf)
#pragma unroll
            for (int nf = 0; nf < 4; ++nf) {
                int r = rbase + mf * 16;
                int c = wn * 32 + nf * 8 + (lane & 3) * 2;
                float2 b2v = *(const float2*)(b2 + k0 + c);
                float2 rv0 = __half22float2(*(const __half2*)(Rbase + (size_t)r * CS + k0 + c));
                float2 rv1 = __half22float2(*(const __half2*)(Rbase + (size_t)(r + 8) * CS + k0 + c));
                accL[mf][nf][0] = fmaf(s2, accL[mf][nf][0] + b2v.x, rv0.x);
                accL[mf][nf][1] = fmaf(s2, accL[mf][nf][1] + b2v.y, rv0.y);
                accL[mf][nf][2] = fmaf(s2, accL[mf][nf][2] + b2v.x, rv1.x);
                accL[mf][nf][3] = fmaf(s2, accL[mf][nf][3] + b2v.y, rv1.y);
            }

        float vmax[2][2];
#pragma unroll
        for (int mf = 0; mf < 2; ++mf) {
            vmax[mf][0] = -INFINITY; vmax[mf][1] = -INFINITY;
#pragma unroll
            for (int nf = 0; nf < 4; ++nf) {
                vmax[mf][0] = fmaxf(vmax[mf][0], fmaxf(accL[mf][nf][0], accL[mf][nf][1]));
                vmax[mf][1] = fmaxf(vmax[mf][1], fmaxf(accL[mf][nf][2], accL[mf][nf][3]));
            }
#pragma unroll
            for (int o = 1; o <= 2; o <<= 1) {
                vmax[mf][0] = fmaxf(vmax[mf][0], __shfl_xor_sync(0xffffffffu, vmax[mf][0], o));
                vmax[mf][1] = fmaxf(vmax[mf][1], __shfl_xor_sync(0xffffffffu, vmax[mf][1], o));
            }
        }
        if ((lane & 3) == 0) {
#pragma unroll
            for (int mf = 0; mf < 2; ++mf) {
                rmax[(rbase + mf * 16) * 4 + wn]     = vmax[mf][0];
                rmax[(rbase + mf * 16 + 8) * 4 + wn] = vmax[mf][1];
            }
        }
        CP_WAIT(0);
        __syncthreads();

        float m_old[2][2], l_old[2][2], m_new[2][2], vsum[2][2];
#pragma unroll
        for (int mf = 0; mf < 2; ++mf)
#pragma unroll
            for (int hf = 0; hf < 2; ++hf) {
                int r = rbase + mf * 16 + hf * 8;
                float mx = fmaxf(fmaxf(rmax[r * 4], rmax[r * 4 + 1]),
                                 fmaxf(rmax[r * 4 + 2], rmax[r * 4 + 3]));
                m_old[mf][hf] = mrow[r];
                l_old[mf][hf] = lrow[r];
                m_new[mf][hf] = fmaxf(m_old[mf][hf], mx);
                vsum[mf][hf] = 0.f;
            }
#pragma unroll
        for (int mf = 0; mf < 2; ++mf)
#pragma unroll
            for (int nf = 0; nf < 4; ++nf) {
                accL[mf][nf][0] = __expf(accL[mf][nf][0] - m_new[mf][0]);
                accL[mf][nf][1] = __expf(accL[mf][nf][1] - m_new[mf][0]);
                accL[mf][nf][2] = __expf(accL[mf][nf][2] - m_new[mf][1]);
                accL[mf][nf][3] = __expf(accL[mf][nf][3] - m_new[mf][1]);
                vsum[mf][0] += accL[mf][nf][0] + accL[mf][nf][1];
                vsum[mf][1] += accL[mf][nf][2] + accL[mf][nf][3];
            }
#pragma unroll
        for (int mf = 0; mf < 2; ++mf)
#pragma unroll
            for (int o = 1; o <= 2; o <<= 1) {
                vsum[mf][0] += __shfl_xor_sync(0xffffffffu, vsum[mf][0], o);
                vsum[mf][1] += __shfl_xor_sync(0xffffffffu, vsum[mf][1], o);
            }
        if ((lane & 3) == 0) {
#pragma unroll
            for (int mf = 0; mf < 2; ++mf) {
                rsum[(rbase + mf * 16) * 4 + wn]     = vsum[mf][0];
                rsum[(rbase + mf * 16 + 8) * 4 + wn] = vsum[mf][1];
            }
        }
        __syncthreads();

        float crow[2][2];
#pragma unroll
        for (int mf = 0; mf < 2; ++mf)
#pragma unroll
            for (int hf = 0; hf < 2; ++hf) {
                int r = rbase + mf * 16 + hf * 8;
                float ssum = rsum[r * 4] + rsum[r * 4 + 1] + rsum[r * 4 + 2] + rsum[r * 4 + 3];
                float cr = __expf(m_old[mf][hf] - m_new[mf][hf]);
                crow[mf][hf] = cr;
                if (wn == 0 && (lane & 3) == 0) {
                    mrow[r] = m_new[mf][hf];
                    lrow[r] = l_old[mf][hf] * cr + ssum;
                }
            }
#pragma unroll
        for (int mf = 0; mf < 2; ++mf)
#pragma unroll
            for (int nf = 0; nf < 2; ++nf) {
                accO[mf][nf][0] *= crow[mf][0]; accO[mf][nf][1] *= crow[mf][0];
                accO[mf][nf][2] *= crow[mf][1]; accO[mf][nf][3] *= crow[mf][1];
            }
#pragma unroll
        for (int mf = 0; mf < 2; ++mf)
#pragma unroll
            for (int nf = 0; nf < 4; ++nf) {
                int r = rbase + mf * 16;
                int c = wn * 32 + nf * 8 + (lane & 3) * 2;
                uint32_t lo, hi;
                hi = pack_split(accL[mf][nf][0], accL[mf][nf][1], lo);
                *(uint32_t*)(dsm + AO_PH + r * PW + c * 2) = hi;
                *(uint32_t*)(dsm + AO_PL + r * PW + c * 2) = lo;
                hi = pack_split(accL[mf][nf][2], accL[mf][nf][3], lo);
                *(uint32_t*)(dsm + AO_PH + (r + 8) * PW + c * 2) = hi;
                *(uint32_t*)(dsm + AO_PL + (r + 8) * PW + c * 2) = lo;
            }
        __syncthreads();

#pragma unroll
        for (int kk = 0; kk < 8; ++kk) {
            uint32_t pah[2][4], pal[2][4], vbh[2][2], vbl[2][2];
#pragma unroll
            for (int mf = 0; mf < 2; ++mf) {
                uint32_t o = aOffP + (uint32_t)mf * (16 * PW) + kk * 32;
                ldsm_x4(pah[mf], sb + AO_PH + o);
                ldsm_x4(pal[mf], sb + AO_PL + o);
            }
            {
                uint32_t o = bOffV + kk * 32;
                uint32_t r4[4];
                ldsm_x4(r4, sb + AO_VH + o);
                vbh[0][0] = r4[0]; vbh[0][1] = r4[1];
                vbh[1][0] = r4[2]; vbh[1][1] = r4[3];
                ldsm_x4(r4, sb + AO_VL + o);
                vbl[0][0] = r4[0]; vbl[0][1] = r4[1];
                vbl[1][0] = r4[2]; vbl[1][1] = r4[3];
            }
#pragma unroll
            for (int mf = 0; mf < 2; ++mf)
#pragma unroll
                for (int nf = 0; nf < 2; ++nf)
                    mma16816(accO[mf][nf], pah[mf], vbh[nf]);
#pragma unroll
            for (int mf = 0; mf < 2; ++mf)
#pragma unroll
                for (int nf = 0; nf < 2; ++nf)
                    mma16816(accO[mf][nf], pah[mf], vbl[nf]);
#pragma unroll
            for (int mf = 0; mf < 2; ++mf)
#pragma unroll
                for (int nf = 0; nf < 2; ++nf)
                    mma16816(accO[mf][nf], pal[mf], vbh[nf]);
        }
        __syncthreads();
    }

#pragma unroll
    for (int mf = 0; mf < 2; ++mf)
#pragma unroll
        for (int nf = 0; nf < 2; ++nf) {
            int r = rbase + mf * 16;
            int d = wn * 16 + nf * 8 + (lane & 3) * 2;
            float i0 = 1.f / lrow[r];
            float i1 = 1.f / lrow[r + 8];
            size_t e0 = ((size_t)(bi * CS) + q0 + r) * 1024 + h * 64 + d;
            size_t e1 = ((size_t)(bi * CS) + q0 + r + 8) * 1024 + h * 64 + d;
            uint32_t lo, hi;
            hi = pack_split(accO[mf][nf][0] * i0, accO[mf][nf][1] * i0, lo);
            *(uint32_t*)(g_AOh + e0) = hi;
            *(uint32_t*)(g_AOl + e0) = lo;
            hi = pack_split(accO[mf][nf][2] * i1, accO[mf][nf][3] * i1, lo);
            *(uint32_t*)(g_AOh + e1) = hi;
            *(uint32_t*)(g_AOl + e1) = lo;
        }
}

// ---------------------------------------------------------------------------
// Launch
// ---------------------------------------------------------------------------
extern "C" void kernel_launch(void* const* d_in, const int* in_sizes, int n_in,
                              void* d_out, int out_size)
{
    const float* query      = (const float*)d_in[0];
    const float* value      = (const float*)d_in[1];
    const float* Wq         = (const float*)d_in[2];
    const float* bq         = (const float*)d_in[3];
    const float* Wv         = (const float*)d_in[4];
    const float* bv         = (const float*)d_in[5];
    const float* W1         = (const float*)d_in[6];
    const float* b1         = (const float*)d_in[7];
    const float* W2         = (const float*)d_in[8];
    const float* b2         = (const float*)d_in[9];
    const float* random_mat = (const float*)d_in[10];
    const float* alpha_one  = (const float*)d_in[11];
    const float* alpha_two  = (const float*)d_in[12];
    const float* Wo         = (const float*)d_in[13];
    const float* bo         = (const float*)d_in[14];
    float* out = (float*)d_out;

    float *Qp, *Vp;
    __half* Rs;
    __nv_bfloat16 *Ah, *Al, *AOh, *AOl, *Wth, *Wtl, *Vth, *Vtl, *W2th, *W2tl;
    cudaGetSymbolAddress((void**)&Qp, g_Qp);
    cudaGetSymbolAddress((void**)&Vp, g_Vp);
    cudaGetSymbolAddress((void**)&Rs, g_Rs);
    cudaGetSymbolAddress((void**)&Ah, g_Ah);
    cudaGetSymbolAddress((void**)&Al, g_Al);
    cudaGetSymbolAddress((void**)&AOh, g_AOh);
    cudaGetSymbolAddress((void**)&AOl, g_AOl);
    cudaGetSymbolAddress((void**)&Wth, g_Wth);
    cudaGetSymbolAddress((void**)&Wtl, g_Wtl);
    cudaGetSymbolAddress((void**)&Vth, g_Vth);
    cudaGetSymbolAddress((void**)&Vtl, g_Vtl);
    cudaGetSymbolAddress((void**)&W2th, g_W2th);
    cudaGetSymbolAddress((void**)&W2tl, g_W2tl);

    cudaFuncSetAttribute(gemm_mma_kernel,
                         cudaFuncAttributeMaxDynamicSharedMemorySize, GEMM_SMEM);
    cudaFuncSetAttribute(synth_attn_mma,
                         cudaFuncAttributeMaxDynamicSharedMemorySize, ATTN_SMEM);

    const dim3 convBlk(32, 8);
    const dim3 gemmGrid(CD / 64, (CB * CS) / 128);   // (16, 32)

    // Q projection
    asplit_kernel<<<4096, 256>>>(query, Ah, Al);
    tsplit_kernel<<<dim3(32, 32, 1), convBlk>>>(Wq, Wth, Wtl, 1024, 1024);
    gemm_mma_kernel<<<gemmGrid, 256, GEMM_SMEM>>>(Ah, Al, Wth, Wtl, bq, Qp, 0);

    // V projection (+ transpose/split for attention)
    asplit_kernel<<<4096, 256>>>(value, Ah, Al);
    tsplit_kernel<<<dim3(32, 32, 1), convBlk>>>(Wv, Wth, Wtl, 1024, 1024);
    gemm_mma_kernel<<<gemmGrid, 256, GEMM_SMEM>>>(Ah, Al, Wth, Wtl, bv, Vp, 0);
    tsplit_kernel<<<dim3(2, 32, 64), convBlk>>>(Vp, Vth, Vtl, 1024, 64);

    // W2 transpose/split
    tsplit_kernel<<<dim3(32, 2, 1), convBlk>>>(W2, W2th, W2tl, 64, 1024);

    // pre-scaled random-branch softmax (fp16 output)
    rand_softmax_kernel<<<CH * CS, 256>>>(random_mat, alpha_one, alpha_two, Rs);

    // fused synthesizer attention (tensor-core, 2 CTAs/SM) -> split-bf16 AO
    synth_attn_mma<<<dim3(CS / 64, CB * CH), 256, ATTN_SMEM>>>(
        W1, b1, W2th, W2tl, b2, Vth, Vtl, alpha_one, alpha_two);

    // output projection (AO already split by attention epilogue)
    tsplit_kernel<<<dim3(32, 32, 1), convBlk>>>(Wo, Wth, Wtl, 1024, 1024);
    gemm_mma_kernel<<<gemmGrid, 256, GEMM_SMEM>>>(AOh, AOl, Wth, Wtl, bo, out, 1);
}

// round 14
// speedup vs baseline: 1.0667x; 1.0667x over previous
#include <cuda_runtime.h>
#include <cuda_bf16.h>
#include <cuda_fp16.h>
#include <cstdint>
#include <math.h>

// Problem constants
#define CB 4
#define CS 1024
#define CD 1024
#define CH 16
#define CHD 64
#define GK 1024   // K of all three big GEMMs

// ---------------------------------------------------------------------------
// Scratch (device globals — no runtime allocation allowed)
// ---------------------------------------------------------------------------
__device__ float g_Qp[(size_t)CB * CH * CS * CHD];       // queries  [b,h,s,k]
__device__ float g_Vp[(size_t)CB * CH * CS * CHD];       // values   [b,h,s,k]
__device__ __half g_Rs[(size_t)CH * CS * CS];            // s1*softmax(random), fp16
__device__ __nv_bfloat16 g_Ah[(size_t)CB * CS * GK];     // A hi (bf16) [m][k]
__device__ __nv_bfloat16 g_Al[(size_t)CB * CS * GK];     // A lo (bf16) [m][k]
__device__ __nv_bfloat16 g_AOh[(size_t)CB * CS * CD];    // attn out hi [m][k]
__device__ __nv_bfloat16 g_AOl[(size_t)CB * CS * CD];    // attn out lo [m][k]
__device__ __nv_bfloat16 g_Wth[(size_t)GK * GK];         // W^T hi (bf16) [n][k]
__device__ __nv_bfloat16 g_Wtl[(size_t)GK * GK];         // W^T lo (bf16) [n][k]
__device__ __half g_Vth[(size_t)CB * CH * CHD * CS];     // V^T hi (fp16) [b,h,d,s]
__device__ __half g_Vtl[(size_t)CB * CH * CHD * CS];     // V^T lo (fp16) [b,h,d,s]
__device__ __nv_bfloat16 g_W2th[(size_t)CS * CHD];       // W2^T hi [t][j]
__device__ __nv_bfloat16 g_W2tl[(size_t)CS * CHD];       // W2^T lo [t][j]

// ---------------------------------------------------------------------------
// Warp-MMA / async-copy helpers (sm_80+ path — compiles at compute_100)
// ---------------------------------------------------------------------------
__device__ __forceinline__ uint32_t smem_u32(const void* p) {
    uint32_t a;
    asm("{ .reg .u64 t; cvta.to.shared.u64 t, %1; cvt.u32.u64 %0, t; }"
        : "=r"(a) : "l"(p));
    return a;
}

__device__ __forceinline__ void ldsm_x4(uint32_t* r, uint32_t addr) {
    asm volatile("ldmatrix.sync.aligned.m8n8.x4.shared.b16 {%0,%1,%2,%3}, [%4];"
                 : "=r"(r[0]), "=r"(r[1]), "=r"(r[2]), "=r"(r[3]) : "r"(addr));
}

__device__ __forceinline__ void mma16816(float* c, const uint32_t* a, const uint32_t* b) {
    asm volatile(
        "mma.sync.aligned.m16n8k16.row.col.f32.bf16.bf16.f32 "
        "{%0,%1,%2,%3}, {%4,%5,%6,%7}, {%8,%9}, {%0,%1,%2,%3};"
        : "+f"(c[0]), "+f"(c[1]), "+f"(c[2]), "+f"(c[3])
        : "r"(a[0]), "r"(a[1]), "r"(a[2]), "r"(a[3]), "r"(b[0]), "r"(b[1]));
}

__device__ __forceinline__ void mma16816h(float* c, const uint32_t* a, const uint32_t* b) {
    asm volatile(
        "mma.sync.aligned.m16n8k16.row.col.f32.f16.f16.f32 "
        "{%0,%1,%2,%3}, {%4,%5,%6,%7}, {%8,%9}, {%0,%1,%2,%3};"
        : "+f"(c[0]), "+f"(c[1]), "+f"(c[2]), "+f"(c[3])
        : "r"(a[0]), "r"(a[1]), "r"(a[2]), "r"(a[3]), "r"(b[0]), "r"(b[1]));
}

__device__ __forceinline__ uint32_t pack_split(float x, float y, uint32_t& lo) {
    __nv_bfloat16 hx = __float2bfloat16(x), hy = __float2bfloat16(y);
    __nv_bfloat16 lx = __float2bfloat16(x - __bfloat162float(hx));
    __nv_bfloat16 ly = __float2bfloat16(y - __bfloat162float(hy));
    lo = (uint32_t)__bfloat16_as_ushort(lx) | ((uint32_t)__bfloat16_as_ushort(ly) << 16);
    return (uint32_t)__bfloat16_as_ushort(hx) | ((uint32_t)__bfloat16_as_ushort(hy) << 16);
}

__device__ __forceinline__ void cp_async16(uint32_t dst, const void* src) {
    asm volatile("cp.async.cg.shared.global [%0], [%1], 16;"
                 :: "r"(dst), "l"(src) : "memory");
}
#define CP_COMMIT() asm volatile("cp.async.commit_group;" ::: "memory")
#define CP_WAIT(n)  asm volatile("cp.async.wait_group %0;" :: "n"(n) : "memory")

// ---------------------------------------------------------------------------
// Elementwise split: h/l[i] = split(src[i]).  1 float4 per thread.
// ---------------------------------------------------------------------------
__global__ void __launch_bounds__(256) asplit_kernel(
    const float* __restrict__ src, __nv_bfloat16* __restrict__ h,
    __nv_bfloat16* __restrict__ l)
{
    int idx = blockIdx.x * 256 + threadIdx.x;     // float4 index
    float4 a = ((const float4*)src)[idx];
    uint2 hv, lv;
    hv.x = pack_split(a.x, a.y, lv.x);
    hv.y = pack_split(a.z, a.w, lv.y);
    ((uint2*)h)[idx] = hv;
    ((uint2*)l)[idx] = lv;
}

// ---------------------------------------------------------------------------
// Generic transpose + split-bf16: dst_hi/lo[c][r] = split(src[r][c]), batched z.
// ---------------------------------------------------------------------------
__global__ void __launch_bounds__(256) tsplit_kernel(
    const float* __restrict__ src, __nv_bfloat16* __restrict__ dh,
    __nv_bfloat16* __restrict__ dl, int R, int C)
{
    __shared__ float t[32][33];
    const size_t zoff = (size_t)blockIdx.z * R * C;
    src += zoff; dh += zoff; dl += zoff;
    const int c0 = blockIdx.x * 32, r0 = blockIdx.y * 32;
    const int tx = threadIdx.x, ty = threadIdx.y;
#pragma unroll
    for (int j = 0; j < 32; j += 8)
        t[ty + j][tx] = src[(size_t)(r0 + ty + j) * C + c0 + tx];
    __syncthreads();
#pragma unroll
    for (int j = 0; j < 32; j += 8) {
        float v = t[tx][ty + j];
        __nv_bfloat16 h = __float2bfloat16(v);
        size_t o = (size_t)(c0 + ty + j) * R + r0 + tx;
        dh[o] = h;
        dl[o] = __float2bfloat16(v - __bfloat162float(h));
    }
}

// fp16 variant (for V)
__global__ void __launch_bounds__(256) tsplit_h_kernel(
    const float* __restrict__ src, __half* __restrict__ dh,
    __half* __restrict__ dl, int R, int C)
{
    __shared__ float t[32][33];
    const size_t zoff = (size_t)blockIdx.z * R * C;
    src += zoff; dh += zoff; dl += zoff;
    const int c0 = blockIdx.x * 32, r0 = blockIdx.y * 32;
    const int tx = threadIdx.x, ty = threadIdx.y;
#pragma unroll
    for (int j = 0; j < 32; j += 8)
        t[ty + j][tx] = src[(size_t)(r0 + ty + j) * C + c0 + tx];
    __syncthreads();
#pragma unroll
    for (int j = 0; j < 32; j += 8) {
        float v = t[tx][ty + j];
        __half h = __float2half_rn(v);
        size_t o = (size_t)(c0 + ty + j) * R + r0 + tx;
        dh[o] = h;
        dl[o] = __float2half_rn(v - __half2float(h));
    }
}

// ---------------------------------------------------------------------------
// Split-bf16 mma.sync GEMM (R10/R12 config: BK=64, 128x128, 2-stage cp.async,
// term-major MMA ordering, occ 1). Best measured config.
// ---------------------------------------------------------------------------
#define SROW 144
#define TILE_B (128 * SROW)
#define STAGE_B (4 * TILE_B)
#define GEMM_SMEM (2 * STAGE_B)

__global__ void __launch_bounds__(256, 1) gemm_mma_kernel(
    const __nv_bfloat16* __restrict__ Ah, const __nv_bfloat16* __restrict__ Al,
    const __nv_bfloat16* __restrict__ Wth, const __nv_bfloat16* __restrict__ Wtl,
    const float* __restrict__ bias, float* __restrict__ out, int mode)
{
    extern __shared__ char dsm[];
    const uint32_t sb = smem_u32(dsm);

    const int tid = threadIdx.x;
    const int lane = tid & 31, wid = tid >> 5;
    const int warp_m = wid & 1;
    const int warp_n = wid >> 1;
    const int m0 = blockIdx.y * 128;
    const int n0 = blockIdx.x * 128;

    const uint32_t aOff = (uint32_t)(warp_m * 64 + (lane & 15)) * SROW + (lane >> 4) * 16;
    const uint32_t bOff = (uint32_t)(warp_n * 32 + (lane & 7) + ((lane >> 4) & 1) * 8) * SROW
                        + ((lane >> 3) & 1) * 16;

    auto stage_load = [&](int s, int buf) {
        const int k0 = s * 64;
        const uint32_t db = sb + buf * STAGE_B;
#pragma unroll
        for (int i = 0; i < 16; ++i) {
            const int tile = i >> 2;
            const int j = (i & 3) * 256 + tid;
            const int row = j >> 3, c8 = j & 7;
            const __nv_bfloat16* src;
            if (tile == 0)      src = Ah  + (size_t)(m0 + row) * GK + k0 + c8 * 8;
            else if (tile == 1) src = Al  + (size_t)(m0 + row) * GK + k0 + c8 * 8;
            else if (tile == 2) src = Wth + (size_t)(n0 + row) * GK + k0 + c8 * 8;
            else                src = Wtl + (size_t)(n0 + row) * GK + k0 + c8 * 8;
            cp_async16(db + tile * TILE_B + (uint32_t)row * SROW + c8 * 16, src);
        }
    };

    float acc[4][4][4] = {};

    stage_load(0, 0);
    CP_COMMIT();

    for (int s = 0; s < 16; ++s) {
        if (s < 15) {
            stage_load(s + 1, (s + 1) & 1);
            CP_COMMIT();
            CP_WAIT(1);
        } else {
            CP_WAIT(0);
        }
        __syncthreads();

        const uint32_t db = sb + (s & 1) * STAGE_B;
        const uint32_t sAh = db, sAl = db + TILE_B;
        const uint32_t sBh = db + 2 * TILE_B, sBl = db + 3 * TILE_B;

#pragma unroll
        for (int kk = 0; kk < 4; ++kk) {
            uint32_t ah[4][4], al[4][4], bh[4][2], bl[4][2];
#pragma unroll
            for (int f = 0; f < 4; ++f) {
                uint32_t o = aOff + (uint32_t)f * (16 * SROW) + kk * 32;
                ldsm_x4(ah[f], sAh + o);
                ldsm_x4(al[f], sAl + o);
            }
#pragma unroll
            for (int g = 0; g < 2; ++g) {
                uint32_t o = bOff + (uint32_t)g * (16 * SROW) + kk * 32;
                uint32_t r[4];
                ldsm_x4(r, sBh + o);
                bh[2 * g][0] = r[0]; bh[2 * g][1] = r[1];
                bh[2 * g + 1][0] = r[2]; bh[2 * g + 1][1] = r[3];
                ldsm_x4(r, sBl + o);
                bl[2 * g][0] = r[0]; bl[2 * g][1] = r[1];
                bl[2 * g + 1][0] = r[2]; bl[2 * g + 1][1] = r[3];
            }
#pragma unroll
            for (int mf = 0; mf < 4; ++mf)
#pragma unroll
                for (int nf = 0; nf < 4; ++nf)
                    mma16816(acc[mf][nf], ah[mf], bh[nf]);
#pragma unroll
            for (int mf = 0; mf < 4; ++mf)
#pragma unroll
                for (int nf = 0; nf < 4; ++nf)
                    mma16816(acc[mf][nf], ah[mf], bl[nf]);
#pragma unroll
            for (int mf = 0; mf < 4; ++mf)
#pragma unroll
                for (int nf = 0; nf < 4; ++nf)
                    mma16816(acc[mf][nf], al[mf], bh[nf]);
        }
        __syncthreads();
    }

#pragma unroll
    for (int mf = 0; mf < 4; ++mf) {
#pragma unroll
        for (int nf = 0; nf < 4; ++nf) {
            int m = m0 + warp_m * 64 + mf * 16 + (lane >> 2);
            int n = n0 + warp_n * 32 + nf * 8 + (lane & 3) * 2;
            float b0 = bias[n], b1 = bias[n + 1];
            float2 v0 = make_float2(acc[mf][nf][0] + b0, acc[mf][nf][1] + b1);
            float2 v1 = make_float2(acc[mf][nf][2] + b0, acc[mf][nf][3] + b1);
            if (mode == 0) {
                int h = n >> 6, kk = n & 63;
                {
                    int b_ = m >> 10, s_ = m & 1023;
                    *(float2*)(out + (((size_t)(b_ * CH + h)) * CS + s_) * CHD + kk) = v0;
                }
                {
                    int m2 = m + 8;
                    int b_ = m2 >> 10, s_ = m2 & 1023;
                    *(float2*)(out + (((size_t)(b_ * CH + h)) * CS + s_) * CHD + kk) = v1;
                }
            } else {
                *(float2*)(out + (size_t)m * CD + n) = v0;
                *(float2*)(out + (size_t)(m + 8) * CD + n) = v1;
            }
        }
    }
}

// ---------------------------------------------------------------------------
// rand softmax: g_Rs[h,q,:] = s1 * softmax(random_mat[h,q,:])  (fp16 output)
// ---------------------------------------------------------------------------
__global__ void __launch_bounds__(256) rand_softmax_kernel(
    const float* __restrict__ rm,
    const float* __restrict__ a1p, const float* __restrict__ a2p,
    __half* __restrict__ out)
{
    __shared__ float red[8];
    const int row = blockIdx.x;
    const int tid = threadIdx.x;
    const int lane = tid & 31, wid = tid >> 5;

    float4 v = ((const float4*)(rm + (size_t)row * 1024))[tid];
    float mx = fmaxf(fmaxf(v.x, v.y), fmaxf(v.z, v.w));
#pragma unroll
    for (int o = 16; o; o >>= 1) mx = fmaxf(mx, __shfl_xor_sync(0xffffffffu, mx, o));
    if (lane == 0) red[wid] = mx;
    __syncthreads();
    float m = red[0];
#pragma unroll
    for (int i = 1; i < 8; ++i) m = fmaxf(m, red[i]);

    float e0 = __expf(v.x - m), e1 = __expf(v.y - m);
    float e2 = __expf(v.z - m), e3 = __expf(v.w - m);
    float s = (e0 + e1) + (e2 + e3);
#pragma unroll
    for (int o = 16; o; o >>= 1) s += __shfl_xor_sync(0xffffffffu, s, o);
    __syncthreads();
    if (lane == 0) red[wid] = s;
    __syncthreads();
    float tot = 0.f;
#pragma unroll
    for (int i = 0; i < 8; ++i) tot += red[i];

    float a1 = a1p[0], a2 = a2p[0];
    float s1 = a1 / (a1 + a2);
    float k = s1 / tot;
    __half2* dst = (__half2*)(out + (size_t)row * 1024);
    dst[tid * 2]     = __floats2half2_rn(e0 * k, e1 * k);
    dst[tid * 2 + 1] = __floats2half2_rn(e2 * k, e3 * k);
}

// ---------------------------------------------------------------------------
// Fused synthesizer attention: register softmax, cp.async, 2 CTAs/SM.
// Logits: split-bf16 3-term. P@V: fp16 P (single) x fp16 split V (2-term).
// ---------------------------------------------------------------------------
#define TW 144
#define PW 272
#define AO_TH   0
#define AO_TL   9216
#define AO_W2H  18432
#define AO_W2L  36864
#define AO_PH   18432              // aliases W2H (W2 dead after logits MMA)
#define AO_VH   55296
#define AO_VL   72704
#define AO_MROW 90112
#define AO_LROW 90368
#define AO_RMAX 90624
#define AO_RSUM 91648
#define ATTN_SMEM 92672

__global__ void __launch_bounds__(256, 2) synth_attn_mma(
    const float* __restrict__ W1, const float* __restrict__ b1,
    const __nv_bfloat16* __restrict__ W2th, const __nv_bfloat16* __restrict__ W2tl,
    const float* __restrict__ b2,
    const __half* __restrict__ Vth, const __half* __restrict__ Vtl,
    const float* __restrict__ a1p, const float* __restrict__ a2p)
{
    extern __shared__ char dsm[];
    const uint32_t sb = smem_u32(dsm);
    float* mrow = (float*)(dsm + AO_MROW);
    float* lrow = (float*)(dsm + AO_LROW);
    float* rmax = (float*)(dsm + AO_RMAX);
    float* rsum = (float*)(dsm + AO_RSUM);

    const int tid = threadIdx.x;
    const int lane = tid & 31, wid = tid >> 5;
    const int wm = wid & 1, wn = wid >> 1;
    const int bh = blockIdx.y;
    const int bi = bh >> 4, h = bh & 15;
    const int q0 = blockIdx.x * 64;

    const float a1 = a1p[0], a2 = a2p[0];
    const float s2 = a2 / (a1 + a2);

    // ---- prologue: T = relu(Q@W1 + b1) -> Th/Tl (temps live in V region) ----
    {
        float* Qs  = (float*)(dsm + AO_VH);
        float* W1s = (float*)(dsm + AO_VH + 16384);
        const float* Qbase = g_Qp + ((size_t)bh * CS + q0) * CHD;
        for (int i = tid; i < 1024; i += 256) {
            ((float4*)Qs)[i]  = ((const float4*)Qbase)[i];
            ((float4*)W1s)[i] = ((const float4*)W1)[i];
        }
        if (tid < 64) { mrow[tid] = -INFINITY; lrow[tid] = 0.f; }
        __syncthreads();

        const int a = tid >> 5, bb = tid & 31;
        float acc[8][2] = {};
#pragma unroll 4
        for (int i = 0; i < 64; ++i) {
            float2 w = *(const float2*)(W1s + i * 64 + 2 * bb);
#pragma unroll
            for (int r = 0; r < 8; ++r) {
                float qv = Qs[(a * 8 + r) * 64 + i];
                acc[r][0] = fmaf(qv, w.x, acc[r][0]);
                acc[r][1] = fmaf(qv, w.y, acc[r][1]);
            }
        }
        float bb0 = b1[2 * bb], bb1 = b1[2 * bb + 1];
        __syncthreads();
#pragma unroll
        for (int r = 0; r < 8; ++r) {
            float t0 = fmaxf(acc[r][0] + bb0, 0.f);
            float t1 = fmaxf(acc[r][1] + bb1, 0.f);
            uint32_t lo, hi = pack_split(t0, t1, lo);
            int q = a * 8 + r;
            *(uint32_t*)(dsm + AO_TH + q * TW + bb * 4) = hi;
            *(uint32_t*)(dsm + AO_TL + q * TW + bb * 4) = lo;
        }
    }
    __syncthreads();

    const uint32_t aOffT = (uint32_t)(wm * 32 + (lane & 15)) * TW + (lane >> 4) * 16;
    const uint32_t bOffW = (uint32_t)(wn * 32 + (lane & 7) + ((lane >> 4) & 1) * 8) * TW
                         + ((lane >> 3) & 1) * 16;
    const uint32_t aOffP = (uint32_t)(wm * 32 + (lane & 15)) * PW + (lane >> 4) * 16;
    const uint32_t bOffV = (uint32_t)(wn * 16 + (lane & 7) + ((lane >> 4) & 1) * 8) * PW
                         + ((lane >> 3) & 1) * 16;

    const __half* Rbase = g_Rs + ((size_t)h * CS + q0) * CS;
    const __half* Vbh = Vth + (size_t)bh * CHD * CS;
    const __half* Vbl = Vtl + (size_t)bh * CHD * CS;

    const int rbase = wm * 32 + (lane >> 2);

    float accO[2][2][4] = {};

    for (int k0 = 0; k0 < 1024; k0 += 128) {
#pragma unroll
        for (int i = 0; i < 4; ++i) {
            int idx = tid + i * 256;
            int row = idx >> 3, c = idx & 7;
            size_t so = (size_t)(k0 + row) * CHD + c * 8;
            cp_async16(sb + AO_W2H + row * TW + c * 16, W2th + so);
            cp_async16(sb + AO_W2L + row * TW + c * 16, W2tl + so);
        }
        CP_COMMIT();
#pragma unroll
        for (int i = 0; i < 4; ++i) {
            int idx = tid + i * 256;
            int row = idx >> 4, c = idx & 15;
            size_t so = (size_t)row * CS + k0 + c * 8;
            cp_async16(sb + AO_VH + row * PW + c * 16, Vbh + so);
            cp_async16(sb + AO_VL + row * PW + c * 16, Vbl + so);
        }
        CP_COMMIT();
        CP_WAIT(1);
        __syncthreads();

        float accL[2][4][4] = {};
#pragma unroll
        for (int kk = 0; kk < 4; ++kk) {
            uint32_t ah[2][4], al[2][4], bhf[4][2], blf[4][2];
#pragma unroll
            for (int mf = 0; mf < 2; ++mf) {
                uint32_t o = aOffT + (uint32_t)mf * (16 * TW) + kk * 32;
                ldsm_x4(ah[mf], sb + AO_TH + o);
                ldsm_x4(al[mf], sb + AO_TL + o);
            }
#pragma unroll
            for (int g = 0; g < 2; ++g) {
                uint32_t o = bOffW + (uint32_t)g * (16 * TW) + kk * 32;
                uint32_t r4[4];
                ldsm_x4(r4, sb + AO_W2H + o);
                bhf[2 * g][0] = r4[0]; bhf[2 * g][1] = r4[1];
                bhf[2 * g + 1][0] = r4[2]; bhf[2 * g + 1][1] = r4[3];
                ldsm_x4(r4, sb + AO_W2L + o);
                blf[2 * g][0] = r4[0]; blf[2 * g][1] = r4[1];
                blf[2 * g + 1][0] = r4[2]; blf[2 * g + 1][1] = r4[3];
            }
#pragma unroll
            for (int mf = 0; mf < 2; ++mf)
#pragma unroll
                for (int nf = 0; nf < 4; ++nf)
                    mma16816(accL[mf][nf], ah[mf], bhf[nf]);
#pragma unroll
            for (int mf = 0; mf < 2; ++mf)
#pragma unroll
                for (int nf = 0; nf < 4; ++nf)
                    mma16816(accL[mf][nf], ah[mf], blf[nf]);
#pragma unroll
            for (int mf = 0; mf < 2; ++mf)
#pragma unroll
                for (int nf = 0; nf < 4; ++nf)
                    mma16816(accL[mf][nf], al[mf], bhf[nf]);
        }

#pragma unroll
        for (int mf = 0; mf < 2; ++mf)
#pragma unroll
            for (int nf = 0; nf < 4; ++nf) {
                int r = rbase + mf * 16;
                int c = wn * 32 + nf * 8 + (lane & 3) * 2;
                float2 b2v = *(const float2*)(b2 + k0 + c);
                float2 rv0 = __half22float2(*(const __half2*)(Rbase + (size_t)r * CS + k0 + c));
                float2 rv1 = __half22float2(*(const __half2*)(Rbase + (size_t)(r + 8) * CS + k0 + c));
                accL[mf][nf][0] = fmaf(s2, accL[mf][nf][0] + b2v.x, rv0.x);
                accL[mf][nf][1] = fmaf(s2, accL[mf][nf][1] + b2v.y, rv0.y);
                accL[mf][nf][2] = fmaf(s2, accL[mf][nf][2] + b2v.x, rv1.x);
                accL[mf][nf][3] = fmaf(s2, accL[mf][nf][3] + b2v.y, rv1.y);
            }

        float vmax[2][2];
#pragma unroll
        for (int mf = 0; mf < 2; ++mf) {
            vmax[mf][0] = -INFINITY; vmax[mf][1] = -INFINITY;
#pragma unroll
            for (int nf = 0; nf < 4; ++nf) {
                vmax[mf][0] = fmaxf(vmax[mf][0], fmaxf(accL[mf][nf][0], accL[mf][nf][1]));
                vmax[mf][1] = fmaxf(vmax[mf][1], fmaxf(accL[mf][nf][2], accL[mf][nf][3]));
            }
#pragma unroll
            for (int o = 1; o <= 2; o <<= 1) {
                vmax[mf][0] = fmaxf(vmax[mf][0], __shfl_xor_sync(0xffffffffu, vmax[mf][0], o));
                vmax[mf][1] = fmaxf(vmax[mf][1], __shfl_xor_sync(0xffffffffu, vmax[mf][1], o));
            }
        }
        if ((lane & 3) == 0) {
#pragma unroll
            for (int mf = 0; mf < 2; ++mf) {
                rmax[(rbase + mf * 16) * 4 + wn]     = vmax[mf][0];
                rmax[(rbase + mf * 16 + 8) * 4 + wn] = vmax[mf][1];
            }
        }
        CP_WAIT(0);
        __syncthreads();

        float m_old[2][2], l_old[2][2], m_new[2][2], vsum[2][2];
#pragma unroll
        for (int mf = 0; mf < 2; ++mf)
#pragma unroll
            for (int hf = 0; hf < 2; ++hf) {
                int r = rbase + mf * 16 + hf * 8;
                float mx = fmaxf(fmaxf(rmax[r * 4], rmax[r * 4 + 1]),
                                 fmaxf(rmax[r * 4 + 2], rmax[r * 4 + 3]));
                m_old[mf][hf] = mrow[r];
                l_old[mf][hf] = lrow[r];
                m_new[mf][hf] = fmaxf(m_old[mf][hf], mx);
                vsum[mf][hf] = 0.f;
            }
#pragma unroll
        for (int mf = 0; mf < 2; ++mf)
#pragma unroll
            for (int nf = 0; nf < 4; ++nf) {
                accL[mf][nf][0] = __expf(accL[mf][nf][0] - m_new[mf][0]);
                accL[mf][nf][1] = __expf(accL[mf][nf][1] - m_new[mf][0]);
                accL[mf][nf][2] = __expf(accL[mf][nf][2] - m_new[mf][1]);
                accL[mf][nf][3] = __expf(accL[mf][nf][3] - m_new[mf][1]);
                vsum[mf][0] += accL[mf][nf][0] + accL[mf][nf][1];
                vsum[mf][1] += accL[mf][nf][2] + accL[mf][nf][3];
            }
#pragma unroll
        for (int mf = 0; mf < 2; ++mf)
#pragma unroll
            for (int o = 1; o <= 2; o <<= 1) {
                vsum[mf][0] += __shfl_xor_sync(0xffffffffu, vsum[mf][0], o);
                vsum[mf][1] += __shfl_xor_sync(0xffffffffu, vsum[mf][1], o);
            }
        if ((lane & 3) == 0) {
#pragma unroll
            for (int mf = 0; mf < 2; ++mf) {
                rsum[(rbase + mf * 16) * 4 + wn]     = vsum[mf][0];
                rsum[(rbase + mf * 16 + 8) * 4 + wn] = vsum[mf][1];
            }
        }
        __syncthreads();

        float crow[2][2];
#pragma unroll
        for (int mf = 0; mf < 2; ++mf)
#pragma unroll
            for (int hf = 0; hf < 2; ++hf) {
                int r = rbase + mf * 16 + hf * 8;
                float ssum = rsum[r * 4] + rsum[r * 4 + 1] + rsum[r * 4 + 2] + rsum[r * 4 + 3];
                float cr = __expf(m_old[mf][hf] - m_new[mf][hf]);
                crow[mf][hf] = cr;
                if (wn == 0 && (lane & 3) == 0) {
                    mrow[r] = m_new[mf][hf];
                    lrow[r] = l_old[mf][hf] * cr + ssum;
                }
            }
#pragma unroll
        for (int mf = 0; mf < 2; ++mf)
#pragma unroll
            for (int nf = 0; nf < 2; ++nf) {
                accO[mf][nf][0] *= crow[mf][0]; accO[mf][nf][1] *= crow[mf][0];
                accO[mf][nf][2] *= crow[mf][1]; accO[mf][nf][3] *= crow[mf][1];
            }
        // pack P as fp16 (single, no split)
#pragma unroll
        for (int mf = 0; mf < 2; ++mf)
#pragma unroll
            for (int nf = 0; nf < 4; ++nf) {
                int r = rbase + mf * 16;
                int c = wn * 32 + nf * 8 + (lane & 3) * 2;
                *(__half2*)(dsm + AO_PH + r * PW + c * 2) =
                    __floats2half2_rn(accL[mf][nf][0], accL[mf][nf][1]);
                *(__half2*)(dsm + AO_PH + (r + 8) * PW + c * 2) =
                    __floats2half2_rn(accL[mf][nf][2], accL[mf][nf][3]);
            }
        __syncthreads();

        // ---- P @ V^T (fp16, 2-term: P*Vh + P*Vl) ----
#pragma unroll
        for (int kk = 0; kk < 8; ++kk) {
            uint32_t pah[2][4], vbh[2][2], vbl[2][2];
#pragma unroll
            for (int mf = 0; mf < 2; ++mf) {
                uint32_t o = aOffP + (uint32_t)mf * (16 * PW) + kk * 32;
                ldsm_x4(pah[mf], sb + AO_PH + o);
            }
            {
                uint32_t o = bOffV + kk * 32;
                uint32_t r4[4];
                ldsm_x4(r4, sb + AO_VH + o);
                vbh[0][0] = r4[0]; vbh[0][1] = r4[1];
                vbh[1][0] = r4[2]; vbh[1][1] = r4[3];
                ldsm_x4(r4, sb + AO_VL + o);
                vbl[0][0] = r4[0]; vbl[0][1] = r4[1];
                vbl[1][0] = r4[2]; vbl[1][1] = r4[3];
            }
#pragma unroll
            for (int mf = 0; mf < 2; ++mf)
#pragma unroll
                for (int nf = 0; nf < 2; ++nf)
                    mma16816h(accO[mf][nf], pah[mf], vbh[nf]);
#pragma unroll
            for (int mf = 0; mf < 2; ++mf)
#pragma unroll
                for (int nf = 0; nf < 2; ++nf)
                    mma16816h(accO[mf][nf], pah[mf], vbl[nf]);
        }
        __syncthreads();
    }

#pragma unroll
    for (int mf = 0; mf < 2; ++mf)
#pragma unroll
        for (int nf = 0; nf < 2; ++nf) {
            int r = rbase + mf * 16;
            int d = wn * 16 + nf * 8 + (lane & 3) * 2;
            float i0 = 1.f / lrow[r];
            float i1 = 1.f / lrow[r + 8];
            size_t e0 = ((size_t)(bi * CS) + q0 + r) * 1024 + h * 64 + d;
            size_t e1 = ((size_t)(bi * CS) + q0 + r + 8) * 1024 + h * 64 + d;
            uint32_t lo, hi;
            hi = pack_split(accO[mf][nf][0] * i0, accO[mf][nf][1] * i0, lo);
            *(uint32_t*)(g_AOh + e0) = hi;
            *(uint32_t*)(g_AOl + e0) = lo;
            hi = pack_split(accO[mf][nf][2] * i1, accO[mf][nf][3] * i1, lo);
            *(uint32_t*)(g_AOh + e1) = hi;
            *(uint32_t*)(g_AOl + e1) = lo;
        }
}

// ---------------------------------------------------------------------------
// Launch
// ---------------------------------------------------------------------------
extern "C" void kernel_launch(void* const* d_in, const int* in_sizes, int n_in,
                              void* d_out, int out_size)
{
    const float* query      = (const float*)d_in[0];
    const float* value      = (const float*)d_in[1];
    const float* Wq         = (const float*)d_in[2];
    const float* bq         = (const float*)d_in[3];
    const float* Wv         = (const float*)d_in[4];
    const float* bv         = (const float*)d_in[5];
    const float* W1         = (const float*)d_in[6];
    const float* b1         = (const float*)d_in[7];
    const float* W2         = (const float*)d_in[8];
    const float* b2         = (const float*)d_in[9];
    const float* random_mat = (const float*)d_in[10];
    const float* alpha_one  = (const float*)d_in[11];
    const float* alpha_two  = (const float*)d_in[12];
    const float* Wo         = (const float*)d_in[13];
    const float* bo         = (const float*)d_in[14];
    float* out = (float*)d_out;

    float *Qp, *Vp;
    __half *Rs, *Vth, *Vtl;
    __nv_bfloat16 *Ah, *Al, *AOh, *AOl, *Wth, *Wtl, *W2th, *W2tl;
    cudaGetSymbolAddress((void**)&Qp, g_Qp);
    cudaGetSymbolAddress((void**)&Vp, g_Vp);
    cudaGetSymbolAddress((void**)&Rs, g_Rs);
    cudaGetSymbolAddress((void**)&Ah, g_Ah);
    cudaGetSymbolAddress((void**)&Al, g_Al);
    cudaGetSymbolAddress((void**)&AOh, g_AOh);
    cudaGetSymbolAddress((void**)&AOl, g_AOl);
    cudaGetSymbolAddress((void**)&Wth, g_Wth);
    cudaGetSymbolAddress((void**)&Wtl, g_Wtl);
    cudaGetSymbolAddress((void**)&Vth, g_Vth);
    cudaGetSymbolAddress((void**)&Vtl, g_Vtl);
    cudaGetSymbolAddress((void**)&W2th, g_W2th);
    cudaGetSymbolAddress((void**)&W2tl, g_W2tl);

    cudaFuncSetAttribute(gemm_mma_kernel,
                         cudaFuncAttributeMaxDynamicSharedMemorySize, GEMM_SMEM);
    cudaFuncSetAttribute(synth_attn_mma,
                         cudaFuncAttributeMaxDynamicSharedMemorySize, ATTN_SMEM);

    const dim3 convBlk(32, 8);
    const dim3 gemmGrid(CD / 128, (CB * CS) / 128);   // (8, 32)

    // Q projection
    asplit_kernel<<<4096, 256>>>(query, Ah, Al);
    tsplit_kernel<<<dim3(32, 32, 1), convBlk>>>(Wq, Wth, Wtl, 1024, 1024);
    gemm_mma_kernel<<<gemmGrid, 256, GEMM_SMEM>>>(Ah, Al, Wth, Wtl, bq, Qp, 0);

    // V projection (+ fp16 transpose/split for attention)
    asplit_kernel<<<4096, 256>>>(value, Ah, Al);
    tsplit_kernel<<<dim3(32, 32, 1), convBlk>>>(Wv, Wth, Wtl, 1024, 1024);
    gemm_mma_kernel<<<gemmGrid, 256, GEMM_SMEM>>>(Ah, Al, Wth, Wtl, bv, Vp, 0);
    tsplit_h_kernel<<<dim3(2, 32, 64), convBlk>>>(Vp, Vth, Vtl, 1024, 64);

    // W2 transpose/split
    tsplit_kernel<<<dim3(32, 2, 1), convBlk>>>(W2, W2th, W2tl, 64, 1024);

    // pre-scaled random-branch softmax (fp16 output)
    rand_softmax_kernel<<<CH * CS, 256>>>(random_mat, alpha_one, alpha_two, Rs);

    // fused synthesizer attention (tensor-core, 2 CTAs/SM) -> split-bf16 AO
    synth_attn_mma<<<dim3(CS / 64, CB * CH), 256, ATTN_SMEM>>>(
        W1, b1, W2th, W2tl, b2, Vth, Vtl, alpha_one, alpha_two);

    // output projection (AO already split by attention epilogue)
    tsplit_kernel<<<dim3(32, 32, 1), convBlk>>>(Wo, Wth, Wtl, 1024, 1024);
    gemm_mma_kernel<<<gemmGrid, 256, GEMM_SMEM>>>(AOh, AOl, Wth, Wtl, bo, out, 1);
}